// round 5
// baseline (speedup 1.0000x reference)
#include <cuda_runtime.h>
#include <math.h>

#define H 128
#define E_MAX 80000
#define N_MAX 40000

// ---------------- scratch (device globals; no allocation allowed) ----------
__device__ __align__(16) float g_Pz [E_MAX * H];
__device__ __align__(16) float g_Pr [E_MAX * H];
__device__ __align__(16) float g_Ph [E_MAX * H];
__device__ __align__(16) float g_q  [E_MAX * H];
__device__ __align__(16) float g_sh [E_MAX * H];
__device__ __align__(16) float g_sg [E_MAX * H];
__device__ __align__(16) float g_hA [E_MAX * H];
__device__ __align__(16) float g_hB [E_MAX * H];
__device__ __align__(16) float g_nei[N_MAX * H];
__device__ int g_bg32[E_MAX * 6];
__device__ int g_ag32[N_MAX * 6];
__device__ int g_idx_is64;

__device__ __forceinline__ float sigmoidf_(float x) { return 1.0f / (1.0f + expf(-x)); }

// ---------------------------------------------------------------------------
// Index dtype handling: JAX without x64 silently downcasts int64 -> int32.
// Detect at runtime: int64 little-endian data with values < 2^31 has zero
// high words at odd int32 positions; int32 index data (random in [0,E)) does
// not. Then normalize both graphs to int32 scratch.
// ---------------------------------------------------------------------------
__global__ void detect_idx_kernel(const unsigned int* __restrict__ w)
{
    g_idx_is64 = (w[1] == 0u && w[3] == 0u && w[5] == 0u && w[7] == 0u) ? 1 : 0;
}

__global__ void convert_idx_kernel(const void* __restrict__ src, int* __restrict__ dst, int n)
{
    int i = blockIdx.x * blockDim.x + threadIdx.x;
    if (i >= n) return;
    if (g_idx_is64) dst[i] = (int)((const long long*)src)[i];
    else            dst[i] = ((const int*)src)[i];
}

// ---------------------------------------------------------------------------
// Shared tiled-GEMM mainloop: acc[4][8] += X[brow:brow+64, :K] @ W[:K, 0:128]
// Block = 256 threads; thread (rg,cg) owns rows rg*4..+3, cols cg*8..+7.
// X row stride must equal K. W row-major [K,128].
// ---------------------------------------------------------------------------
__device__ __forceinline__ void gemm_tile_loop(
    const float* __restrict__ X, int K, const float* __restrict__ W,
    float (*Xs)[68], float (*Ws)[128], float acc[4][8],
    int brow, int M, int tid, int rg, int cg)
{
    const int row = tid >> 2;            // 0..63
    const int kv  = (tid & 3) * 4;       // 0,4,8,12
    const int gr  = brow + row;

    for (int k0 = 0; k0 < K; k0 += 16) {
        float4 v = make_float4(0.f, 0.f, 0.f, 0.f);
        if (gr < M) v = *(const float4*)&X[(size_t)gr * K + k0 + kv];
        Xs[kv + 0][row] = v.x; Xs[kv + 1][row] = v.y;
        Xs[kv + 2][row] = v.z; Xs[kv + 3][row] = v.w;

        const float4* wg = (const float4*)&W[(size_t)k0 * H];
        ((float4*)Ws)[tid]       = wg[tid];
        ((float4*)Ws)[tid + 256] = wg[tid + 256];
        __syncthreads();

#pragma unroll
        for (int k = 0; k < 16; ++k) {
            const float4 xv = *(const float4*)&Xs[k][rg * 4];
            const float4 wa = *(const float4*)&Ws[k][cg * 8];
            const float4 wb = *(const float4*)&Ws[k][cg * 8 + 4];
            const float xs[4] = {xv.x, xv.y, xv.z, xv.w};
            const float ws[8] = {wa.x, wa.y, wa.z, wa.w, wb.x, wb.y, wb.z, wb.w};
#pragma unroll
            for (int r = 0; r < 4; ++r)
#pragma unroll
                for (int c = 0; c < 8; ++c)
                    acc[r][c] = fmaf(xs[r], ws[c], acc[r][c]);
        }
        __syncthreads();
    }
}

// out[M,128] = X[M,K] @ W[K,128] (+ bias)
__global__ void __launch_bounds__(256)
gemm_bias_kernel(const float* __restrict__ X, const float* __restrict__ W,
                 const float* __restrict__ bias, float* __restrict__ out,
                 int M, int K)
{
    __shared__ float Xs[16][68];
    __shared__ float Ws[16][128];
    const int tid  = threadIdx.x;
    const int brow = blockIdx.x * 64;
    const int rg = tid >> 4, cg = tid & 15;
    float acc[4][8] = {};

    gemm_tile_loop(X, K, W, Xs, Ws, acc, brow, M, tid, rg, cg);

    float bv[8];
#pragma unroll
    for (int c = 0; c < 8; ++c) bv[c] = bias ? bias[cg * 8 + c] : 0.f;

#pragma unroll
    for (int r = 0; r < 4; ++r) {
        const int row = brow + rg * 4 + r;
        if (row >= M) continue;
        const size_t base = (size_t)row * H + cg * 8;
        float4 o1, o2;
        o1.x = acc[r][0] + bv[0]; o1.y = acc[r][1] + bv[1];
        o1.z = acc[r][2] + bv[2]; o1.w = acc[r][3] + bv[3];
        o2.x = acc[r][4] + bv[4]; o2.y = acc[r][5] + bv[5];
        o2.z = acc[r][6] + bv[6]; o2.w = acc[r][7] + bv[7];
        *(float4*)&out[base]     = o1;
        *(float4*)&out[base + 4] = o2;
    }
}

// iteration 1 (h == 0): h1 = sigmoid(Pz) * tanh(Ph), row 0 masked
__global__ void iter1_kernel(const float* __restrict__ Pz, const float* __restrict__ Ph,
                             float* __restrict__ hout, int total)
{
    int i = blockIdx.x * blockDim.x + threadIdx.x;
    if (i >= total) return;
    float v = sigmoidf_(Pz[i]) * tanhf(Ph[i]);
    if (i < H) v = 0.f;   // edge row 0 is padding
    hout[i] = v;
}

// per-edge neighbor gather: sumh = sum_j h[bg[j]], sumg = sum_j sigmoid(Pr+q[bg[j]])*h[bg[j]]
__global__ void edge_gather_kernel(const float* __restrict__ h, const float* __restrict__ q,
                                   const int* __restrict__ bgraph,
                                   const float* __restrict__ Pr,
                                   float* __restrict__ sumh, float* __restrict__ sumg, int E)
{
    const int e = blockIdx.x * blockDim.y + threadIdx.y;
    if (e >= E) return;
    const int c4 = threadIdx.x * 4;     // 32 lanes * 4 = 128 cols
    const float4 pr = *(const float4*)&Pr[(size_t)e * H + c4];
    float4 sh = make_float4(0.f, 0.f, 0.f, 0.f);
    float4 sg = make_float4(0.f, 0.f, 0.f, 0.f);
#pragma unroll
    for (int j = 0; j < 6; ++j) {
        const int idx = __ldg(&bgraph[e * 6 + j]);
        const float4 hn = *(const float4*)&h[(size_t)idx * H + c4];
        const float4 qn = *(const float4*)&q[(size_t)idx * H + c4];
        sh.x += hn.x; sh.y += hn.y; sh.z += hn.z; sh.w += hn.w;
        sg.x += hn.x * sigmoidf_(pr.x + qn.x);
        sg.y += hn.y * sigmoidf_(pr.y + qn.y);
        sg.z += hn.z * sigmoidf_(pr.z + qn.z);
        sg.w += hn.w * sigmoidf_(pr.w + qn.w);
    }
    *(float4*)&sumh[(size_t)e * H + c4] = sh;
    *(float4*)&sumg[(size_t)e * H + c4] = sg;
}

// fused GRU update: z = sig(sumh@Wz2 + Pz); p = tanh(sumg@Wh2 + Ph);
// h_new = (1-z)*sumh + z*p, row 0 masked.
__global__ void __launch_bounds__(256)
gru_update_kernel(const float* __restrict__ SH, const float* __restrict__ SG,
                  const float* __restrict__ Wz2, const float* __restrict__ Wh2,
                  const float* __restrict__ Pz, const float* __restrict__ Ph,
                  float* __restrict__ hout, int M)
{
    __shared__ float Xs[16][68];
    __shared__ float Ws[16][128];
    const int tid  = threadIdx.x;
    const int brow = blockIdx.x * 64;
    const int rg = tid >> 4, cg = tid & 15;

    float accZ[4][8] = {};
    gemm_tile_loop(SH, H, Wz2, Xs, Ws, accZ, brow, M, tid, rg, cg);
    float accH[4][8] = {};
    gemm_tile_loop(SG, H, Wh2, Xs, Ws, accH, brow, M, tid, rg, cg);

#pragma unroll
    for (int r = 0; r < 4; ++r) {
        const int row = brow + rg * 4 + r;
        if (row >= M) continue;
        const size_t base = (size_t)row * H + cg * 8;
        float o[8];
#pragma unroll
        for (int c = 0; c < 8; ++c) {
            const float z   = sigmoidf_(accZ[r][c] + Pz[base + c]);
            const float p   = tanhf(accH[r][c] + Ph[base + c]);
            const float shv = SH[base + c];
            o[c] = (row == 0) ? 0.f : (1.f - z) * shv + z * p;
        }
        *(float4*)&hout[base]     = make_float4(o[0], o[1], o[2], o[3]);
        *(float4*)&hout[base + 4] = make_float4(o[4], o[5], o[6], o[7]);
    }
}

// per-node neighbor gather: nei[n] = sum_j h[agraph[n,j]]
__global__ void node_gather_kernel(const float* __restrict__ h,
                                   const int* __restrict__ agraph,
                                   float* __restrict__ nei, int N)
{
    const int n = blockIdx.x * blockDim.y + threadIdx.y;
    if (n >= N) return;
    const int c4 = threadIdx.x * 4;
    float4 s = make_float4(0.f, 0.f, 0.f, 0.f);
#pragma unroll
    for (int j = 0; j < 6; ++j) {
        const int idx = __ldg(&agraph[n * 6 + j]);
        const float4 hn = *(const float4*)&h[(size_t)idx * H + c4];
        s.x += hn.x; s.y += hn.y; s.z += hn.z; s.w += hn.w;
    }
    *(float4*)&nei[(size_t)n * H + c4] = s;
}

// out = relu(fnode @ Wo[0:256] + nei @ Wo[256:384] + bo), row 0 masked
__global__ void __launch_bounds__(256)
node_out_kernel(const float* __restrict__ fnode, const float* __restrict__ Wo,
                const float* __restrict__ nei, const float* __restrict__ bo,
                float* __restrict__ out, int M)
{
    __shared__ float Xs[16][68];
    __shared__ float Ws[16][128];
    const int tid  = threadIdx.x;
    const int brow = blockIdx.x * 64;
    const int rg = tid >> 4, cg = tid & 15;

    float acc[4][8] = {};
    gemm_tile_loop(fnode, 256, Wo,           Xs, Ws, acc, brow, M, tid, rg, cg);
    gemm_tile_loop(nei,   128, Wo + 256 * H, Xs, Ws, acc, brow, M, tid, rg, cg);

    float bv[8];
#pragma unroll
    for (int c = 0; c < 8; ++c) bv[c] = bo[cg * 8 + c];

#pragma unroll
    for (int r = 0; r < 4; ++r) {
        const int row = brow + rg * 4 + r;
        if (row >= M) continue;
        const size_t base = (size_t)row * H + cg * 8;
        float o[8];
#pragma unroll
        for (int c = 0; c < 8; ++c) {
            float v = acc[r][c] + bv[c];
            v = v > 0.f ? v : 0.f;
            o[c] = (row == 0) ? 0.f : v;
        }
        *(float4*)&out[base]     = make_float4(o[0], o[1], o[2], o[3]);
        *(float4*)&out[base + 4] = make_float4(o[4], o[5], o[6], o[7]);
    }
}

// ---------------------------------------------------------------------------
extern "C" void kernel_launch(void* const* d_in, const int* in_sizes, int n_in,
                              void* d_out, int out_size)
{
    const float* fnode  = (const float*) d_in[0];
    const float* fmess  = (const float*) d_in[1];
    const void*  agraph = d_in[2];
    const void*  bgraph = d_in[3];
    const float* Wz     = (const float*) d_in[4];
    const float* bz     = (const float*) d_in[5];
    const float* Wr     = (const float*) d_in[6];
    const float* Ur     = (const float*) d_in[7];
    const float* bur    = (const float*) d_in[8];
    const float* Wh     = (const float*) d_in[9];
    const float* bh     = (const float*) d_in[10];
    const float* Wo     = (const float*) d_in[11];
    const float* bo     = (const float*) d_in[12];

    const int N = in_sizes[2] / 6;   // agraph rows
    const int E = in_sizes[3] / 6;   // bgraph rows

    float *Pz, *Pr, *Ph, *q, *sh, *sg, *hA, *hB, *nei;
    int *bg32, *ag32;
    cudaGetSymbolAddress((void**)&Pz,   g_Pz);
    cudaGetSymbolAddress((void**)&Pr,   g_Pr);
    cudaGetSymbolAddress((void**)&Ph,   g_Ph);
    cudaGetSymbolAddress((void**)&q,    g_q);
    cudaGetSymbolAddress((void**)&sh,   g_sh);
    cudaGetSymbolAddress((void**)&sg,   g_sg);
    cudaGetSymbolAddress((void**)&hA,   g_hA);
    cudaGetSymbolAddress((void**)&hB,   g_hB);
    cudaGetSymbolAddress((void**)&nei,  g_nei);
    cudaGetSymbolAddress((void**)&bg32, g_bg32);
    cudaGetSymbolAddress((void**)&ag32, g_ag32);

    // final h destination: into d_out if the harness scores both outputs,
    // otherwise scratch (output = node_hiddens only).
    float* out_node = (float*)d_out;                           // [N,128]
    const long long need = (long long)(N + E) * H;
    const bool out_has_h = ((long long)out_size >= need);
    float* h_final = out_has_h ? ((float*)d_out + (size_t)N * H) : hA;

    // normalize graph index dtype (JAX may ship int32 despite int64 in source)
    detect_idx_kernel<<<1, 1>>>((const unsigned int*)bgraph);
    convert_idx_kernel<<<(E * 6 + 255) / 256, 256>>>(bgraph, bg32, E * 6);
    convert_idx_kernel<<<(N * 6 + 255) / 256, 256>>>(agraph, ag32, N * 6);

    const int gE = (E + 63) / 64;
    const int gN = (N + 63) / 64;
    const dim3 gb(32, 8);
    const int gbE = (E + 7) / 8;
    const int gbN = (N + 7) / 8;

    // loop-invariant precompute: Pz/Pr/Ph = fmess @ {Wz1,Wr,Wh1} + {bz,bur,bh}
    gemm_bias_kernel<<<gE, 256>>>(fmess, Wz, bz,  Pz, E, 384);
    gemm_bias_kernel<<<gE, 256>>>(fmess, Wr, bur, Pr, E, 384);
    gemm_bias_kernel<<<gE, 256>>>(fmess, Wh, bh,  Ph, E, 384);

    // iteration 1 (h = 0): pure elementwise
    iter1_kernel<<<(E * H + 255) / 256, 256>>>(Pz, Ph, hA, E * H);

    // iteration 2
    gemm_bias_kernel<<<gE, 256>>>(hA, Ur, nullptr, q, E, H);
    edge_gather_kernel<<<gbE, gb>>>(hA, q, bg32, Pr, sh, sg, E);
    gru_update_kernel<<<gE, 256>>>(sh, sg, Wz + 384 * H, Wh + 384 * H, Pz, Ph, hB, E);

    // iteration 3 — final h
    gemm_bias_kernel<<<gE, 256>>>(hB, Ur, nullptr, q, E, H);
    edge_gather_kernel<<<gbE, gb>>>(hB, q, bg32, Pr, sh, sg, E);
    gru_update_kernel<<<gE, 256>>>(sh, sg, Wz + 384 * H, Wh + 384 * H, Pz, Ph, h_final, E);

    // output head
    node_gather_kernel<<<gbN, gb>>>(h_final, ag32, nei, N);
    node_out_kernel<<<gN, 256>>>(fnode, Wo, nei, bo, out_node, N);
}

// round 6
// speedup vs baseline: 2.3062x; 2.3062x over previous
#include <cuda_runtime.h>
#include <math.h>

#define H 128
#define E_MAX 80000
#define N_MAX 40000

// ---------------- scratch (device globals; no allocation allowed) ----------
__device__ __align__(16) float g_Pz [E_MAX * H];
__device__ __align__(16) float g_Pr [E_MAX * H];
__device__ __align__(16) float g_Ph [E_MAX * H];
__device__ __align__(16) float g_q  [E_MAX * H];
__device__ __align__(16) float g_sh [E_MAX * H];
__device__ __align__(16) float g_sg [E_MAX * H];
__device__ __align__(16) float g_hA [E_MAX * H];
__device__ __align__(16) float g_hB [E_MAX * H];
__device__ __align__(16) float g_nei[N_MAX * H];
__device__ int g_bg32[E_MAX * 6];
__device__ int g_ag32[N_MAX * 6];
__device__ int g_idx_is64;

__device__ __forceinline__ float sigmoidf_(float x) { return 1.0f / (1.0f + expf(-x)); }
__device__ __forceinline__ unsigned f2tf32(float f) {
    unsigned u; asm("cvt.rna.tf32.f32 %0, %1;" : "=r"(u) : "f"(f)); return u;
}

// ---------------------------------------------------------------------------
// Index dtype normalize (JAX may ship int32 despite int64 in source).
// ---------------------------------------------------------------------------
__global__ void detect_idx_kernel(const unsigned int* __restrict__ w)
{
    g_idx_is64 = (w[1] == 0u && w[3] == 0u && w[5] == 0u && w[7] == 0u) ? 1 : 0;
}
__global__ void convert_idx_kernel(const void* __restrict__ src, int* __restrict__ dst, int n)
{
    int i = blockIdx.x * blockDim.x + threadIdx.x;
    if (i >= n) return;
    if (g_idx_is64) dst[i] = (int)((const long long*)src)[i];
    else            dst[i] = ((const int*)src)[i];
}

// ---------------------------------------------------------------------------
// tf32 warp-MMA mainloop.  Block = 256 threads.
// Computes C[block tile] += X[brow:brow+BM, :K] @ W[:K, 0:128]  (W row-major
// [K,128]).  Block tile = BM x 128, warps arranged (8/WCOLS) x WCOLS,
// warp tile = (MT*16) x (NT*8).  Smem pads: Xs stride 20, Ws stride 136
// (conflict-free fragment loads).
// ---------------------------------------------------------------------------
#define MMA_TF32(C, a, b) \
    asm volatile("mma.sync.aligned.m16n8k8.row.col.f32.tf32.tf32.f32 " \
        "{%0,%1,%2,%3},{%4,%5,%6,%7},{%8,%9},{%0,%1,%2,%3};" \
        : "+f"((C)[0]), "+f"((C)[1]), "+f"((C)[2]), "+f"((C)[3]) \
        : "r"((a)[0]), "r"((a)[1]), "r"((a)[2]), "r"((a)[3]), \
          "r"((b)[0]), "r"((b)[1]))

template<int BM, int MT, int NT, int WCOLS>
__device__ __forceinline__ void mma_mainloop(
    const float* __restrict__ X, int ldx, int M, int brow,
    const float* __restrict__ W, int K,
    unsigned (*Xs)[20], unsigned (*Ws)[136],
    float (&C)[MT][NT][4])
{
    const int tid  = threadIdx.x;
    const int warp = tid >> 5, lane = tid & 31;
    const int gid  = lane >> 2, tig = lane & 3;
    const int wr   = (warp / WCOLS) * (MT * 16);
    const int wc   = (warp % WCOLS) * (NT * 8);

    for (int k0 = 0; k0 < K; k0 += 16) {
        // ---- stage X tile [BM x 16] (cvt to tf32 during copy) ----
        if (BM == 128) {
            const int row = tid >> 1, cb = (tid & 1) * 8;
            const int gr  = brow + row;
            float4 v0 = make_float4(0.f,0.f,0.f,0.f), v1 = v0;
            if (gr < M) {
                const float* p = X + (size_t)gr * ldx + k0 + cb;
                v0 = *(const float4*)p; v1 = *(const float4*)(p + 4);
            }
            unsigned* d = &Xs[row][cb];
            d[0]=f2tf32(v0.x); d[1]=f2tf32(v0.y); d[2]=f2tf32(v0.z); d[3]=f2tf32(v0.w);
            d[4]=f2tf32(v1.x); d[5]=f2tf32(v1.y); d[6]=f2tf32(v1.z); d[7]=f2tf32(v1.w);
        } else { // BM == 64
            const int row = tid >> 2, cb = (tid & 3) * 4;
            const int gr  = brow + row;
            float4 v0 = make_float4(0.f,0.f,0.f,0.f);
            if (gr < M) v0 = *(const float4*)(X + (size_t)gr * ldx + k0 + cb);
            unsigned* d = &Xs[row][cb];
            d[0]=f2tf32(v0.x); d[1]=f2tf32(v0.y); d[2]=f2tf32(v0.z); d[3]=f2tf32(v0.w);
        }
        // ---- stage W tile [16 x 128] ----
        {
            const int row = tid >> 4, cb = (tid & 15) * 8;
            const float* p = W + (size_t)(k0 + row) * H + cb;
            const float4 v0 = *(const float4*)p, v1 = *(const float4*)(p + 4);
            unsigned* d = &Ws[row][cb];
            d[0]=f2tf32(v0.x); d[1]=f2tf32(v0.y); d[2]=f2tf32(v0.z); d[3]=f2tf32(v0.w);
            d[4]=f2tf32(v1.x); d[5]=f2tf32(v1.y); d[6]=f2tf32(v1.z); d[7]=f2tf32(v1.w);
        }
        __syncthreads();

#pragma unroll
        for (int ks = 0; ks < 16; ks += 8) {
            unsigned a[MT][4], b[NT][2];
#pragma unroll
            for (int mi = 0; mi < MT; ++mi) {
                a[mi][0] = Xs[wr + mi*16 + gid    ][ks + tig    ];
                a[mi][1] = Xs[wr + mi*16 + gid + 8][ks + tig    ];
                a[mi][2] = Xs[wr + mi*16 + gid    ][ks + tig + 4];
                a[mi][3] = Xs[wr + mi*16 + gid + 8][ks + tig + 4];
            }
#pragma unroll
            for (int ni = 0; ni < NT; ++ni) {
                b[ni][0] = Ws[ks + tig    ][wc + ni*8 + gid];
                b[ni][1] = Ws[ks + tig + 4][wc + ni*8 + gid];
            }
#pragma unroll
            for (int mi = 0; mi < MT; ++mi)
#pragma unroll
                for (int ni = 0; ni < NT; ++ni)
                    MMA_TF32(C[mi][ni], a[mi], b[ni]);
        }
        __syncthreads();
    }
}

// ---------------------------------------------------------------------------
// Kernel: out[y] = X @ W[y] (+ bias[y]);   y = blockIdx.y selects weight set.
// BM=128, warp tile 32x64 (MT=2, NT=8), warps 4x2.
// ---------------------------------------------------------------------------
__global__ void __launch_bounds__(256)
mm3_kernel(const float* __restrict__ X, int ldx, int M, int K,
           const float* __restrict__ W0, const float* __restrict__ W1, const float* __restrict__ W2,
           const float* __restrict__ b0, const float* __restrict__ b1, const float* __restrict__ b2,
           float* __restrict__ o0, float* __restrict__ o1, float* __restrict__ o2)
{
    __shared__ unsigned Xs[128][20];
    __shared__ unsigned Ws[16][136];

    const float* W   = (blockIdx.y == 0) ? W0 : (blockIdx.y == 1) ? W1 : W2;
    const float* bia = (blockIdx.y == 0) ? b0 : (blockIdx.y == 1) ? b1 : b2;
    float*       out = (blockIdx.y == 0) ? o0 : (blockIdx.y == 1) ? o1 : o2;

    const int brow = blockIdx.x * 128;
    float C[2][8][4];
#pragma unroll
    for (int i = 0; i < 2; ++i)
#pragma unroll
        for (int j = 0; j < 8; ++j)
#pragma unroll
            for (int k = 0; k < 4; ++k) C[i][j][k] = 0.f;

    mma_mainloop<128, 2, 8, 2>(X, ldx, M, brow, W, K, Xs, Ws, C);

    const int tid = threadIdx.x, warp = tid >> 5, lane = tid & 31;
    const int gid = lane >> 2, tig = lane & 3;
    const int wr = (warp >> 1) * 32, wc = (warp & 1) * 64;

#pragma unroll
    for (int mi = 0; mi < 2; ++mi) {
#pragma unroll
        for (int ni = 0; ni < 8; ++ni) {
            const int col = wc + ni * 8 + 2 * tig;
            const float bx = bia ? bia[col] : 0.f;
            const float by = bia ? bia[col + 1] : 0.f;
            const int r0 = brow + wr + mi * 16 + gid;
            const int r1 = r0 + 8;
            if (r0 < M) *(float2*)&out[(size_t)r0 * H + col] =
                make_float2(C[mi][ni][0] + bx, C[mi][ni][1] + by);
            if (r1 < M) *(float2*)&out[(size_t)r1 * H + col] =
                make_float2(C[mi][ni][2] + bx, C[mi][ni][3] + by);
        }
    }
}

// ---------------------------------------------------------------------------
// Kernel: fused GRU update (tensor core).  BM=64, warp tile 32x32 (MT=2,NT=4),
// warps 2x4.  z = sig(SH@Wz2 + Pz); p = tanh(SG@Wh2 + Ph);
// h_new = (1-z)*SH + z*p; row 0 masked.
// ---------------------------------------------------------------------------
__global__ void __launch_bounds__(256)
gru_update_mma(const float* __restrict__ SH, const float* __restrict__ SG,
               const float* __restrict__ Wz2, const float* __restrict__ Wh2,
               const float* __restrict__ Pz, const float* __restrict__ Ph,
               float* __restrict__ hout, int M)
{
    __shared__ unsigned Xs[64][20];
    __shared__ unsigned Ws[16][136];

    const int brow = blockIdx.x * 64;
    float Cz[2][4][4], Ch[2][4][4];
#pragma unroll
    for (int i = 0; i < 2; ++i)
#pragma unroll
        for (int j = 0; j < 4; ++j)
#pragma unroll
            for (int k = 0; k < 4; ++k) { Cz[i][j][k] = 0.f; Ch[i][j][k] = 0.f; }

    mma_mainloop<64, 2, 4, 4>(SH, H, M, brow, Wz2, H, Xs, Ws, Cz);
    mma_mainloop<64, 2, 4, 4>(SG, H, M, brow, Wh2, H, Xs, Ws, Ch);

    const int tid = threadIdx.x, warp = tid >> 5, lane = tid & 31;
    const int gid = lane >> 2, tig = lane & 3;
    const int wr = (warp >> 2) * 32, wc = (warp & 3) * 32;

#pragma unroll
    for (int mi = 0; mi < 2; ++mi) {
#pragma unroll
        for (int ni = 0; ni < 4; ++ni) {
            const int col = wc + ni * 8 + 2 * tig;
#pragma unroll
            for (int half = 0; half < 2; ++half) {
                const int row = brow + wr + mi * 16 + gid + half * 8;
                if (row >= M) continue;
                const size_t base = (size_t)row * H + col;
                const float2 pz = *(const float2*)&Pz[base];
                const float2 ph = *(const float2*)&Ph[base];
                const float2 sh = *(const float2*)&SH[base];
                const float z0 = sigmoidf_(Cz[mi][ni][half*2+0] + pz.x);
                const float z1 = sigmoidf_(Cz[mi][ni][half*2+1] + pz.y);
                const float p0 = tanhf(Ch[mi][ni][half*2+0] + ph.x);
                const float p1 = tanhf(Ch[mi][ni][half*2+1] + ph.y);
                float o0 = (1.f - z0) * sh.x + z0 * p0;
                float o1 = (1.f - z1) * sh.y + z1 * p1;
                if (row == 0) { o0 = 0.f; o1 = 0.f; }
                *(float2*)&hout[base] = make_float2(o0, o1);
            }
        }
    }
}

// ---------------------------------------------------------------------------
// Kernel: node output head (tensor core).  BM=128 config.
// out = relu(fnode @ Wo[0:256] + nei @ Wo[256:384] + bo), row 0 masked.
// ---------------------------------------------------------------------------
__global__ void __launch_bounds__(256)
node_out_mma(const float* __restrict__ fnode, const float* __restrict__ Wo,
             const float* __restrict__ nei, const float* __restrict__ bo,
             float* __restrict__ out, int M)
{
    __shared__ unsigned Xs[128][20];
    __shared__ unsigned Ws[16][136];

    const int brow = blockIdx.x * 128;
    float C[2][8][4];
#pragma unroll
    for (int i = 0; i < 2; ++i)
#pragma unroll
        for (int j = 0; j < 8; ++j)
#pragma unroll
            for (int k = 0; k < 4; ++k) C[i][j][k] = 0.f;

    mma_mainloop<128, 2, 8, 2>(fnode, 256, M, brow, Wo,           256, Xs, Ws, C);
    mma_mainloop<128, 2, 8, 2>(nei,   H,   M, brow, Wo + 256 * H, H,   Xs, Ws, C);

    const int tid = threadIdx.x, warp = tid >> 5, lane = tid & 31;
    const int gid = lane >> 2, tig = lane & 3;
    const int wr = (warp >> 1) * 32, wc = (warp & 1) * 64;

#pragma unroll
    for (int mi = 0; mi < 2; ++mi) {
#pragma unroll
        for (int ni = 0; ni < 8; ++ni) {
            const int col = wc + ni * 8 + 2 * tig;
            const float bx = bo[col], by = bo[col + 1];
#pragma unroll
            for (int half = 0; half < 2; ++half) {
                const int row = brow + wr + mi * 16 + gid + half * 8;
                if (row >= M) continue;
                float o0 = fmaxf(C[mi][ni][half*2+0] + bx, 0.f);
                float o1 = fmaxf(C[mi][ni][half*2+1] + by, 0.f);
                if (row == 0) { o0 = 0.f; o1 = 0.f; }
                *(float2*)&out[(size_t)row * H + col] = make_float2(o0, o1);
            }
        }
    }
}

// ---------------------------------------------------------------------------
// iteration 1 (h == 0): h1 = sigmoid(Pz) * tanh(Ph), row 0 masked
// ---------------------------------------------------------------------------
__global__ void iter1_kernel(const float* __restrict__ Pz, const float* __restrict__ Ph,
                             float* __restrict__ hout, int total)
{
    int i = blockIdx.x * blockDim.x + threadIdx.x;
    if (i >= total) return;
    float v = sigmoidf_(Pz[i]) * tanhf(Ph[i]);
    if (i < H) v = 0.f;
    hout[i] = v;
}

// per-edge gather: sumh = sum_j h[bg[j]], sumg = sum_j sigmoid(Pr+q[bg[j]])*h[bg[j]]
__global__ void edge_gather_kernel(const float* __restrict__ h, const float* __restrict__ q,
                                   const int* __restrict__ bgraph,
                                   const float* __restrict__ Pr,
                                   float* __restrict__ sumh, float* __restrict__ sumg, int E)
{
    const int e = blockIdx.x * blockDim.y + threadIdx.y;
    if (e >= E) return;
    const int c4 = threadIdx.x * 4;
    const float4 pr = *(const float4*)&Pr[(size_t)e * H + c4];
    float4 sh = make_float4(0.f,0.f,0.f,0.f);
    float4 sg = make_float4(0.f,0.f,0.f,0.f);
#pragma unroll
    for (int j = 0; j < 6; ++j) {
        const int idx = __ldg(&bgraph[e * 6 + j]);
        const float4 hn = *(const float4*)&h[(size_t)idx * H + c4];
        const float4 qn = *(const float4*)&q[(size_t)idx * H + c4];
        sh.x += hn.x; sh.y += hn.y; sh.z += hn.z; sh.w += hn.w;
        sg.x += hn.x * sigmoidf_(pr.x + qn.x);
        sg.y += hn.y * sigmoidf_(pr.y + qn.y);
        sg.z += hn.z * sigmoidf_(pr.z + qn.z);
        sg.w += hn.w * sigmoidf_(pr.w + qn.w);
    }
    *(float4*)&sumh[(size_t)e * H + c4] = sh;
    *(float4*)&sumg[(size_t)e * H + c4] = sg;
}

// per-node gather: nei[n] = sum_j h[agraph[n,j]]
__global__ void node_gather_kernel(const float* __restrict__ h,
                                   const int* __restrict__ agraph,
                                   float* __restrict__ nei, int N)
{
    const int n = blockIdx.x * blockDim.y + threadIdx.y;
    if (n >= N) return;
    const int c4 = threadIdx.x * 4;
    float4 s = make_float4(0.f,0.f,0.f,0.f);
#pragma unroll
    for (int j = 0; j < 6; ++j) {
        const int idx = __ldg(&agraph[n * 6 + j]);
        const float4 hn = *(const float4*)&h[(size_t)idx * H + c4];
        s.x += hn.x; s.y += hn.y; s.z += hn.z; s.w += hn.w;
    }
    *(float4*)&nei[(size_t)n * H + c4] = s;
}

// ---------------------------------------------------------------------------
extern "C" void kernel_launch(void* const* d_in, const int* in_sizes, int n_in,
                              void* d_out, int out_size)
{
    const float* fnode  = (const float*) d_in[0];
    const float* fmess  = (const float*) d_in[1];
    const void*  agraph = d_in[2];
    const void*  bgraph = d_in[3];
    const float* Wz     = (const float*) d_in[4];
    const float* bz     = (const float*) d_in[5];
    const float* Wr     = (const float*) d_in[6];
    const float* Ur     = (const float*) d_in[7];
    const float* bur    = (const float*) d_in[8];
    const float* Wh     = (const float*) d_in[9];
    const float* bh     = (const float*) d_in[10];
    const float* Wo     = (const float*) d_in[11];
    const float* bo     = (const float*) d_in[12];

    const int N = in_sizes[2] / 6;
    const int E = in_sizes[3] / 6;

    float *Pz, *Pr, *Ph, *q, *sh, *sg, *hA, *hB, *nei;
    int *bg32, *ag32;
    cudaGetSymbolAddress((void**)&Pz,   g_Pz);
    cudaGetSymbolAddress((void**)&Pr,   g_Pr);
    cudaGetSymbolAddress((void**)&Ph,   g_Ph);
    cudaGetSymbolAddress((void**)&q,    g_q);
    cudaGetSymbolAddress((void**)&sh,   g_sh);
    cudaGetSymbolAddress((void**)&sg,   g_sg);
    cudaGetSymbolAddress((void**)&hA,   g_hA);
    cudaGetSymbolAddress((void**)&hB,   g_hB);
    cudaGetSymbolAddress((void**)&nei,  g_nei);
    cudaGetSymbolAddress((void**)&bg32, g_bg32);
    cudaGetSymbolAddress((void**)&ag32, g_ag32);

    float* out_node = (float*)d_out;
    const long long need = (long long)(N + E) * H;
    const bool out_has_h = ((long long)out_size >= need);
    float* h_final = out_has_h ? ((float*)d_out + (size_t)N * H) : hA;

    detect_idx_kernel<<<1, 1>>>((const unsigned int*)bgraph);
    convert_idx_kernel<<<(E * 6 + 255) / 256, 256>>>(bgraph, bg32, E * 6);
    convert_idx_kernel<<<(N * 6 + 255) / 256, 256>>>(agraph, ag32, N * 6);

    const int gE128 = (E + 127) / 128;
    const int gE64  = (E + 63) / 64;
    const int gN128 = (N + 127) / 128;
    const dim3 gb(32, 8);
    const int gbE = (E + 7) / 8;
    const int gbN = (N + 7) / 8;

    // loop-invariant precompute (one fused launch, tensor cores):
    // Pz/Pr/Ph = fmess @ {Wz[0:384], Wr, Wh[0:384]} + {bz, bur, bh}
    mm3_kernel<<<dim3(gE128, 3), 256>>>(fmess, 384, E, 384,
                                        Wz, Wr, Wh, bz, bur, bh, Pz, Pr, Ph);

    // iteration 1 (h = 0): elementwise
    iter1_kernel<<<(E * H + 255) / 256, 256>>>(Pz, Ph, hA, E * H);

    // iteration 2
    mm3_kernel<<<dim3(gE128, 1), 256>>>(hA, H, E, H,
                                        Ur, Ur, Ur, nullptr, nullptr, nullptr, q, q, q);
    edge_gather_kernel<<<gbE, gb>>>(hA, q, bg32, Pr, sh, sg, E);
    gru_update_mma<<<gE64, 256>>>(sh, sg, Wz + 384 * H, Wh + 384 * H, Pz, Ph, hB, E);

    // iteration 3 — final h
    mm3_kernel<<<dim3(gE128, 1), 256>>>(hB, H, E, H,
                                        Ur, Ur, Ur, nullptr, nullptr, nullptr, q, q, q);
    edge_gather_kernel<<<gbE, gb>>>(hB, q, bg32, Pr, sh, sg, E);
    gru_update_mma<<<gE64, 256>>>(sh, sg, Wz + 384 * H, Wh + 384 * H, Pz, Ph, h_final, E);

    // output head
    node_gather_kernel<<<gbN, gb>>>(h_final, ag32, nei, N);
    node_out_mma<<<gN128, 256>>>(fnode, Wo, nei, bo, out_node, N);
}

// round 7
// speedup vs baseline: 2.3899x; 1.0363x over previous
#include <cuda_runtime.h>
#include <math.h>

#define H 128
#define E_MAX 80000
#define N_MAX 40000

// ---------------- scratch (device globals; no allocation allowed) ----------
__device__ __align__(16) float g_Pz [E_MAX * H];
__device__ __align__(16) float g_Pr [E_MAX * H];
__device__ __align__(16) float g_Ph [E_MAX * H];
__device__ __align__(16) float g_q1 [E_MAX * H];
__device__ __align__(16) float g_q2 [E_MAX * H];
__device__ __align__(16) float g_hA [E_MAX * H];
__device__ __align__(16) float g_hB [E_MAX * H];
__device__ int g_bg32[E_MAX * 6];
__device__ int g_ag32[N_MAX * 6];
__device__ int g_idx_is64;

__device__ __forceinline__ float sigmoidf_(float x) { return 1.0f / (1.0f + expf(-x)); }
__device__ __forceinline__ unsigned f2tf32(float f) {
    unsigned u; asm("cvt.rna.tf32.f32 %0, %1;" : "=r"(u) : "f"(f)); return u;
}
__device__ __forceinline__ float ftf32(float f) {
    unsigned u; asm("cvt.rna.tf32.f32 %0, %1;" : "=r"(u) : "f"(f));
    return __uint_as_float(u);
}

#define MMA_TF32(C, a, b) \
    asm volatile("mma.sync.aligned.m16n8k8.row.col.f32.tf32.tf32.f32 " \
        "{%0,%1,%2,%3},{%4,%5,%6,%7},{%8,%9},{%0,%1,%2,%3};" \
        : "+f"((C)[0]), "+f"((C)[1]), "+f"((C)[2]), "+f"((C)[3]) \
        : "r"((a)[0]), "r"((a)[1]), "r"((a)[2]), "r"((a)[3]), \
          "r"((b)[0]), "r"((b)[1]))

// ---------------------------------------------------------------------------
// Index dtype normalize (JAX may ship int32 despite int64 in source).
// ---------------------------------------------------------------------------
__global__ void detect_idx_kernel(const unsigned int* __restrict__ w)
{
    g_idx_is64 = (w[1] == 0u && w[3] == 0u && w[5] == 0u && w[7] == 0u) ? 1 : 0;
}
__global__ void convert_idx_kernel(const void* __restrict__ src, int* __restrict__ dst, int n)
{
    int i = blockIdx.x * blockDim.x + threadIdx.x;
    if (i >= n) return;
    if (g_idx_is64) dst[i] = (int)((const long long*)src)[i];
    else            dst[i] = ((const int*)src)[i];
}

// ---------------------------------------------------------------------------
// GEMM helper: A resident in smem (tf32 values stored as float, stride 132),
// C += A[.., k] @ W[k, 128] over K=128.  Wb is the staging buffer.
// Warp tile = 32 x (NT*8); wr/wc give the warp's row/col origin.
// ---------------------------------------------------------------------------
template<int NT>
__device__ __forceinline__ void gemm_smemA(
    const float (*As)[132], const float* __restrict__ W,
    unsigned (*Wb)[136], float (&C)[2][NT][4],
    int wr, int wc, int gid, int tig, int tid)
{
    for (int k0 = 0; k0 < 128; k0 += 16) {
        // stage W tile [16 x 128] with tf32 cvt
        {
            const int row = tid >> 4, cb = (tid & 15) * 8;
            const float* p = W + (size_t)(k0 + row) * H + cb;
            const float4 v0 = *(const float4*)p, v1 = *(const float4*)(p + 4);
            unsigned* d = &Wb[row][cb];
            d[0]=f2tf32(v0.x); d[1]=f2tf32(v0.y); d[2]=f2tf32(v0.z); d[3]=f2tf32(v0.w);
            d[4]=f2tf32(v1.x); d[5]=f2tf32(v1.y); d[6]=f2tf32(v1.z); d[7]=f2tf32(v1.w);
        }
        __syncthreads();
#pragma unroll
        for (int ks = 0; ks < 16; ks += 8) {
            unsigned a[2][4], b[NT][2];
#pragma unroll
            for (int mi = 0; mi < 2; ++mi) {
                a[mi][0] = __float_as_uint(As[wr + mi*16 + gid    ][k0 + ks + tig    ]);
                a[mi][1] = __float_as_uint(As[wr + mi*16 + gid + 8][k0 + ks + tig    ]);
                a[mi][2] = __float_as_uint(As[wr + mi*16 + gid    ][k0 + ks + tig + 4]);
                a[mi][3] = __float_as_uint(As[wr + mi*16 + gid + 8][k0 + ks + tig + 4]);
            }
#pragma unroll
            for (int ni = 0; ni < NT; ++ni) {
                b[ni][0] = Wb[ks + tig    ][wc + ni*8 + gid];
                b[ni][1] = Wb[ks + tig + 4][wc + ni*8 + gid];
            }
#pragma unroll
            for (int mi = 0; mi < 2; ++mi)
#pragma unroll
                for (int ni = 0; ni < NT; ++ni)
                    MMA_TF32(C[mi][ni], a[mi], b[ni]);
        }
        __syncthreads();
    }
}

// ---------------------------------------------------------------------------
// mm3: out[y] = X @ W[y] + bias[y]   (global-A, BM=128, proven from R6)
// ---------------------------------------------------------------------------
__global__ void __launch_bounds__(256)
mm3_kernel(const float* __restrict__ X, int ldx, int M, int K,
           const float* __restrict__ W0, const float* __restrict__ W1, const float* __restrict__ W2,
           const float* __restrict__ b0, const float* __restrict__ b1, const float* __restrict__ b2,
           float* __restrict__ o0, float* __restrict__ o1, float* __restrict__ o2)
{
    __shared__ unsigned Xs[128][20];
    __shared__ unsigned Ws[16][136];

    const float* W   = (blockIdx.y == 0) ? W0 : (blockIdx.y == 1) ? W1 : W2;
    const float* bia = (blockIdx.y == 0) ? b0 : (blockIdx.y == 1) ? b1 : b2;
    float*       out = (blockIdx.y == 0) ? o0 : (blockIdx.y == 1) ? o1 : o2;

    const int tid = threadIdx.x, warp = tid >> 5, lane = tid & 31;
    const int gid = lane >> 2, tig = lane & 3;
    const int wr = (warp >> 1) * 32, wc = (warp & 1) * 64;
    const int brow = blockIdx.x * 128;

    float C[2][8][4];
#pragma unroll
    for (int i = 0; i < 2; ++i)
#pragma unroll
        for (int j = 0; j < 8; ++j)
#pragma unroll
            for (int k = 0; k < 4; ++k) C[i][j][k] = 0.f;

    for (int k0 = 0; k0 < K; k0 += 16) {
        {
            const int row = tid >> 1, cb = (tid & 1) * 8;
            const int gr  = brow + row;
            float4 v0 = make_float4(0.f,0.f,0.f,0.f), v1 = v0;
            if (gr < M) {
                const float* p = X + (size_t)gr * ldx + k0 + cb;
                v0 = *(const float4*)p; v1 = *(const float4*)(p + 4);
            }
            unsigned* d = &Xs[row][cb];
            d[0]=f2tf32(v0.x); d[1]=f2tf32(v0.y); d[2]=f2tf32(v0.z); d[3]=f2tf32(v0.w);
            d[4]=f2tf32(v1.x); d[5]=f2tf32(v1.y); d[6]=f2tf32(v1.z); d[7]=f2tf32(v1.w);
        }
        {
            const int row = tid >> 4, cb = (tid & 15) * 8;
            const float* p = W + (size_t)(k0 + row) * H + cb;
            const float4 v0 = *(const float4*)p, v1 = *(const float4*)(p + 4);
            unsigned* d = &Ws[row][cb];
            d[0]=f2tf32(v0.x); d[1]=f2tf32(v0.y); d[2]=f2tf32(v0.z); d[3]=f2tf32(v0.w);
            d[4]=f2tf32(v1.x); d[5]=f2tf32(v1.y); d[6]=f2tf32(v1.z); d[7]=f2tf32(v1.w);
        }
        __syncthreads();
#pragma unroll
        for (int ks = 0; ks < 16; ks += 8) {
            unsigned a[2][4], b[8][2];
#pragma unroll
            for (int mi = 0; mi < 2; ++mi) {
                a[mi][0] = Xs[wr + mi*16 + gid    ][ks + tig    ];
                a[mi][1] = Xs[wr + mi*16 + gid + 8][ks + tig    ];
                a[mi][2] = Xs[wr + mi*16 + gid    ][ks + tig + 4];
                a[mi][3] = Xs[wr + mi*16 + gid + 8][ks + tig + 4];
            }
#pragma unroll
            for (int ni = 0; ni < 8; ++ni) {
                b[ni][0] = Ws[ks + tig    ][wc + ni*8 + gid];
                b[ni][1] = Ws[ks + tig + 4][wc + ni*8 + gid];
            }
#pragma unroll
            for (int mi = 0; mi < 2; ++mi)
#pragma unroll
                for (int ni = 0; ni < 8; ++ni)
                    MMA_TF32(C[mi][ni], a[mi], b[ni]);
        }
        __syncthreads();
    }

#pragma unroll
    for (int mi = 0; mi < 2; ++mi)
#pragma unroll
        for (int ni = 0; ni < 8; ++ni) {
            const int col = wc + ni * 8 + 2 * tig;
            const float bx = bia ? bia[col] : 0.f;
            const float by = bia ? bia[col + 1] : 0.f;
            const int r0 = brow + wr + mi * 16 + gid;
            const int r1 = r0 + 8;
            if (r0 < M) *(float2*)&out[(size_t)r0 * H + col] =
                make_float2(C[mi][ni][0] + bx, C[mi][ni][1] + by);
            if (r1 < M) *(float2*)&out[(size_t)r1 * H + col] =
                make_float2(C[mi][ni][2] + bx, C[mi][ni][3] + by);
        }
}

// ---------------------------------------------------------------------------
// fused_iter1: h = sigmoid(Pz)*tanh(Ph) (row0 mask) -> global + smem(tf32);
// then q = h @ Ur.   BM=64, warps 2x4 (warp tile 32x32).
// ---------------------------------------------------------------------------
__global__ void __launch_bounds__(256)
fused_iter1_kernel(const float* __restrict__ Pz, const float* __restrict__ Ph,
                   const float* __restrict__ Ur,
                   float* __restrict__ h_out, float* __restrict__ q_out, int E)
{
    __shared__ float As[64][132];
    __shared__ unsigned Wb[16][136];

    const int tid = threadIdx.x, lane = tid & 31, ty = tid >> 5;
    const int gid = lane >> 2, tig = lane & 3;
    const int wr = (ty >> 2) * 32, wc = (ty & 3) * 32;
    const int brow = blockIdx.x * 64;
    const int c4 = lane * 4;

    // phase 1: elementwise h
#pragma unroll
    for (int pass = 0; pass < 8; ++pass) {
        const int er = pass * 8 + ty;
        const int e  = brow + er;
        float4 v = make_float4(0.f,0.f,0.f,0.f);
        if (e < E) {
            const float4 pz = *(const float4*)&Pz[(size_t)e*H + c4];
            const float4 ph = *(const float4*)&Ph[(size_t)e*H + c4];
            v.x = sigmoidf_(pz.x) * tanhf(ph.x);
            v.y = sigmoidf_(pz.y) * tanhf(ph.y);
            v.z = sigmoidf_(pz.z) * tanhf(ph.z);
            v.w = sigmoidf_(pz.w) * tanhf(ph.w);
            if (e == 0) v = make_float4(0.f,0.f,0.f,0.f);
            *(float4*)&h_out[(size_t)e*H + c4] = v;
        }
        *(float4*)&As[er][c4] = make_float4(ftf32(v.x), ftf32(v.y), ftf32(v.z), ftf32(v.w));
    }
    __syncthreads();

    // phase 2: q = h @ Ur
    float C[2][4][4];
#pragma unroll
    for (int i = 0; i < 2; ++i)
#pragma unroll
        for (int j = 0; j < 4; ++j)
#pragma unroll
            for (int k = 0; k < 4; ++k) C[i][j][k] = 0.f;
    gemm_smemA<4>(As, Ur, Wb, C, wr, wc, gid, tig, tid);

#pragma unroll
    for (int mi = 0; mi < 2; ++mi)
#pragma unroll
        for (int ni = 0; ni < 4; ++ni) {
            const int col = wc + ni * 8 + 2 * tig;
            const int r0 = brow + wr + mi * 16 + gid;
            const int r1 = r0 + 8;
            if (r0 < E) *(float2*)&q_out[(size_t)r0 * H + col] =
                make_float2(C[mi][ni][0], C[mi][ni][1]);
            if (r1 < E) *(float2*)&q_out[(size_t)r1 * H + col] =
                make_float2(C[mi][ni][2], C[mi][ni][3]);
        }
}

// ---------------------------------------------------------------------------
// fused_gru: gather(sh,sg) -> smem; Cz=sh@Wz2, Ch=sg@Wh2; GRU epilogue ->
// h_out (fp32 global) + smem(tf32); optional q_out = h_new @ Ur.
// BM=32, warps 1x8 (warp tile 32x16).
// ---------------------------------------------------------------------------
__global__ void __launch_bounds__(256)
fused_gru_kernel(const float* __restrict__ h_in, const float* __restrict__ q_in,
                 const int* __restrict__ bg,
                 const float* __restrict__ Pr, const float* __restrict__ Pz,
                 const float* __restrict__ Ph,
                 const float* __restrict__ Wz2, const float* __restrict__ Wh2,
                 const float* __restrict__ Ur,
                 float* __restrict__ h_out, float* __restrict__ q_out,
                 int E, int do_q)
{
    __shared__ float SHs[32][132];
    __shared__ float SGs[32][132];
    __shared__ unsigned Wb[16][136];

    const int tid = threadIdx.x, lane = tid & 31, ty = tid >> 5;
    const int gid = lane >> 2, tig = lane & 3;
    const int wc = ty * 16;
    const int brow = blockIdx.x * 32;
    const int c4 = lane * 4;

    // gather phase: 32 edges, 6 neighbors each
#pragma unroll
    for (int pass = 0; pass < 4; ++pass) {
        const int er = pass * 8 + ty;
        const int e  = brow + er;
        float4 sh = make_float4(0.f,0.f,0.f,0.f);
        float4 sg = make_float4(0.f,0.f,0.f,0.f);
        if (e < E) {
            const float4 pr = *(const float4*)&Pr[(size_t)e*H + c4];
#pragma unroll
            for (int j = 0; j < 6; ++j) {
                const int idx = __ldg(&bg[e * 6 + j]);
                const float4 hn = *(const float4*)&h_in[(size_t)idx*H + c4];
                const float4 qn = *(const float4*)&q_in[(size_t)idx*H + c4];
                sh.x += hn.x; sh.y += hn.y; sh.z += hn.z; sh.w += hn.w;
                sg.x += hn.x * sigmoidf_(pr.x + qn.x);
                sg.y += hn.y * sigmoidf_(pr.y + qn.y);
                sg.z += hn.z * sigmoidf_(pr.z + qn.z);
                sg.w += hn.w * sigmoidf_(pr.w + qn.w);
            }
        }
        *(float4*)&SHs[er][c4] = make_float4(ftf32(sh.x), ftf32(sh.y), ftf32(sh.z), ftf32(sh.w));
        *(float4*)&SGs[er][c4] = make_float4(ftf32(sg.x), ftf32(sg.y), ftf32(sg.z), ftf32(sg.w));
    }

    float Cz[2][2][4], Ch[2][2][4];
#pragma unroll
    for (int i = 0; i < 2; ++i)
#pragma unroll
        for (int j = 0; j < 2; ++j)
#pragma unroll
            for (int k = 0; k < 4; ++k) { Cz[i][j][k] = 0.f; Ch[i][j][k] = 0.f; }

    gemm_smemA<2>(SHs, Wz2, Wb, Cz, 0, wc, gid, tig, tid);
    gemm_smemA<2>(SGs, Wh2, Wb, Ch, 0, wc, gid, tig, tid);

    // GRU epilogue; write h_out, refill SHs with tf32(h_new) for q-GEMM
#pragma unroll
    for (int mi = 0; mi < 2; ++mi)
#pragma unroll
        for (int ni = 0; ni < 2; ++ni) {
            const int col = wc + ni * 8 + 2 * tig;
#pragma unroll
            for (int half = 0; half < 2; ++half) {
                const int lr  = mi * 16 + gid + half * 8;
                const int row = brow + lr;
                if (row >= E) continue;
                const size_t base = (size_t)row * H + col;
                const float2 pz = *(const float2*)&Pz[base];
                const float2 ph = *(const float2*)&Ph[base];
                const float sh0 = SHs[lr][col], sh1 = SHs[lr][col + 1];
                const float z0 = sigmoidf_(Cz[mi][ni][half*2+0] + pz.x);
                const float z1 = sigmoidf_(Cz[mi][ni][half*2+1] + pz.y);
                const float p0 = tanhf(Ch[mi][ni][half*2+0] + ph.x);
                const float p1 = tanhf(Ch[mi][ni][half*2+1] + ph.y);
                float o0 = (1.f - z0) * sh0 + z0 * p0;
                float o1 = (1.f - z1) * sh1 + z1 * p1;
                if (row == 0) { o0 = 0.f; o1 = 0.f; }
                *(float2*)&h_out[base] = make_float2(o0, o1);
                SHs[lr][col]     = ftf32(o0);
                SHs[lr][col + 1] = ftf32(o1);
            }
        }
    if (!do_q) return;
    __syncthreads();

    // q = h_new @ Ur
    float Cq[2][2][4];
#pragma unroll
    for (int i = 0; i < 2; ++i)
#pragma unroll
        for (int j = 0; j < 2; ++j)
#pragma unroll
            for (int k = 0; k < 4; ++k) Cq[i][j][k] = 0.f;
    gemm_smemA<2>(SHs, Ur, Wb, Cq, 0, wc, gid, tig, tid);

#pragma unroll
    for (int mi = 0; mi < 2; ++mi)
#pragma unroll
        for (int ni = 0; ni < 2; ++ni) {
            const int col = wc + ni * 8 + 2 * tig;
            const int r0 = brow + mi * 16 + gid;
            const int r1 = r0 + 8;
            if (r0 < E) *(float2*)&q_out[(size_t)r0 * H + col] =
                make_float2(Cq[mi][ni][0], Cq[mi][ni][1]);
            if (r1 < E) *(float2*)&q_out[(size_t)r1 * H + col] =
                make_float2(Cq[mi][ni][2], Cq[mi][ni][3]);
        }
}

// ---------------------------------------------------------------------------
// fused_node: C = fnode @ Wo[0:256] (global-A chunks) + gather(nei) @ Wo[256:384]
// epilogue relu(+bo), row0 mask.  BM=64, warps 2x4.
// ---------------------------------------------------------------------------
__global__ void __launch_bounds__(256)
fused_node_kernel(const float* __restrict__ fnode, const float* __restrict__ Wo,
                  const float* __restrict__ h, const int* __restrict__ ag,
                  const float* __restrict__ bo, float* __restrict__ out, int N)
{
    __shared__ float As[64][132];
    __shared__ unsigned Wb[16][136];

    const int tid = threadIdx.x, lane = tid & 31, ty = tid >> 5;
    const int gid = lane >> 2, tig = lane & 3;
    const int wr = (ty >> 2) * 32, wc = (ty & 3) * 32;
    const int brow = blockIdx.x * 64;
    const int c4 = lane * 4;

    float C[2][4][4];
#pragma unroll
    for (int i = 0; i < 2; ++i)
#pragma unroll
        for (int j = 0; j < 4; ++j)
#pragma unroll
            for (int k = 0; k < 4; ++k) C[i][j][k] = 0.f;

    // phase A: fnode @ Wo[0:256], chunked global-A staging into As cols [0,16)
    for (int k0 = 0; k0 < 256; k0 += 16) {
        {
            const int row = tid >> 2, cb = (tid & 3) * 4;
            const int gr  = brow + row;
            float4 v = make_float4(0.f,0.f,0.f,0.f);
            if (gr < N) v = *(const float4*)&fnode[(size_t)gr * 256 + k0 + cb];
            *(float4*)&As[row][cb] = make_float4(ftf32(v.x), ftf32(v.y), ftf32(v.z), ftf32(v.w));
        }
        {
            const int row = tid >> 4, cb = (tid & 15) * 8;
            const float* p = Wo + (size_t)(k0 + row) * H + cb;
            const float4 v0 = *(const float4*)p, v1 = *(const float4*)(p + 4);
            unsigned* d = &Wb[row][cb];
            d[0]=f2tf32(v0.x); d[1]=f2tf32(v0.y); d[2]=f2tf32(v0.z); d[3]=f2tf32(v0.w);
            d[4]=f2tf32(v1.x); d[5]=f2tf32(v1.y); d[6]=f2tf32(v1.z); d[7]=f2tf32(v1.w);
        }
        __syncthreads();
#pragma unroll
        for (int ks = 0; ks < 16; ks += 8) {
            unsigned a[2][4], b[4][2];
#pragma unroll
            for (int mi = 0; mi < 2; ++mi) {
                a[mi][0] = __float_as_uint(As[wr + mi*16 + gid    ][ks + tig    ]);
                a[mi][1] = __float_as_uint(As[wr + mi*16 + gid + 8][ks + tig    ]);
                a[mi][2] = __float_as_uint(As[wr + mi*16 + gid    ][ks + tig + 4]);
                a[mi][3] = __float_as_uint(As[wr + mi*16 + gid + 8][ks + tig + 4]);
            }
#pragma unroll
            for (int ni = 0; ni < 4; ++ni) {
                b[ni][0] = Wb[ks + tig    ][wc + ni*8 + gid];
                b[ni][1] = Wb[ks + tig + 4][wc + ni*8 + gid];
            }
#pragma unroll
            for (int mi = 0; mi < 2; ++mi)
#pragma unroll
                for (int ni = 0; ni < 4; ++ni)
                    MMA_TF32(C[mi][ni], a[mi], b[ni]);
        }
        __syncthreads();
    }

    // phase B: gather nei into As (full width, tf32)
#pragma unroll
    for (int pass = 0; pass < 8; ++pass) {
        const int nr = pass * 8 + ty;
        const int n  = brow + nr;
        float4 s = make_float4(0.f,0.f,0.f,0.f);
        if (n < N) {
#pragma unroll
            for (int j = 0; j < 6; ++j) {
                const int idx = __ldg(&ag[n * 6 + j]);
                const float4 hn = *(const float4*)&h[(size_t)idx*H + c4];
                s.x += hn.x; s.y += hn.y; s.z += hn.z; s.w += hn.w;
            }
        }
        *(float4*)&As[nr][c4] = make_float4(ftf32(s.x), ftf32(s.y), ftf32(s.z), ftf32(s.w));
    }
    __syncthreads();

    gemm_smemA<4>(As, Wo + 256 * H, Wb, C, wr, wc, gid, tig, tid);

#pragma unroll
    for (int mi = 0; mi < 2; ++mi)
#pragma unroll
        for (int ni = 0; ni < 4; ++ni) {
            const int col = wc + ni * 8 + 2 * tig;
            const float bx = bo[col], by = bo[col + 1];
#pragma unroll
            for (int half = 0; half < 2; ++half) {
                const int row = brow + wr + mi * 16 + gid + half * 8;
                if (row >= N) continue;
                float o0 = fmaxf(C[mi][ni][half*2+0] + bx, 0.f);
                float o1 = fmaxf(C[mi][ni][half*2+1] + by, 0.f);
                if (row == 0) { o0 = 0.f; o1 = 0.f; }
                *(float2*)&out[(size_t)row * H + col] = make_float2(o0, o1);
            }
        }
}

// ---------------------------------------------------------------------------
extern "C" void kernel_launch(void* const* d_in, const int* in_sizes, int n_in,
                              void* d_out, int out_size)
{
    const float* fnode  = (const float*) d_in[0];
    const float* fmess  = (const float*) d_in[1];
    const void*  agraph = d_in[2];
    const void*  bgraph = d_in[3];
    const float* Wz     = (const float*) d_in[4];
    const float* bz     = (const float*) d_in[5];
    const float* Wr     = (const float*) d_in[6];
    const float* Ur     = (const float*) d_in[7];
    const float* bur    = (const float*) d_in[8];
    const float* Wh     = (const float*) d_in[9];
    const float* bh     = (const float*) d_in[10];
    const float* Wo     = (const float*) d_in[11];
    const float* bo     = (const float*) d_in[12];

    const int N = in_sizes[2] / 6;
    const int E = in_sizes[3] / 6;

    float *Pz, *Pr, *Ph, *q1, *q2, *hA, *hB;
    int *bg32, *ag32;
    cudaGetSymbolAddress((void**)&Pz,   g_Pz);
    cudaGetSymbolAddress((void**)&Pr,   g_Pr);
    cudaGetSymbolAddress((void**)&Ph,   g_Ph);
    cudaGetSymbolAddress((void**)&q1,   g_q1);
    cudaGetSymbolAddress((void**)&q2,   g_q2);
    cudaGetSymbolAddress((void**)&hA,   g_hA);
    cudaGetSymbolAddress((void**)&hB,   g_hB);
    cudaGetSymbolAddress((void**)&bg32, g_bg32);
    cudaGetSymbolAddress((void**)&ag32, g_ag32);

    float* out_node = (float*)d_out;
    const long long need = (long long)(N + E) * H;
    const bool out_has_h = ((long long)out_size >= need);
    float* h_final = out_has_h ? ((float*)d_out + (size_t)N * H) : hA;

    detect_idx_kernel<<<1, 1>>>((const unsigned int*)bgraph);
    convert_idx_kernel<<<(E * 6 + 255) / 256, 256>>>(bgraph, bg32, E * 6);
    convert_idx_kernel<<<(N * 6 + 255) / 256, 256>>>(agraph, ag32, N * 6);

    const int gE128 = (E + 127) / 128;
    const int gE64  = (E + 63) / 64;
    const int gE32  = (E + 31) / 32;
    const int gN64  = (N + 63) / 64;

    // loop-invariant precompute (tensor cores, one launch):
    mm3_kernel<<<dim3(gE128, 3), 256>>>(fmess, 384, E, 384,
                                        Wz, Wr, Wh, bz, bur, bh, Pz, Pr, Ph);

    // iteration 1 (h=0): elementwise h + fused q = h@Ur
    fused_iter1_kernel<<<gE64, 256>>>(Pz, Ph, Ur, hA, q1, E);

    // iteration 2: gather + dual GEMM + GRU + fused q
    fused_gru_kernel<<<gE32, 256>>>(hA, q1, bg32, Pr, Pz, Ph,
                                    Wz + 384 * H, Wh + 384 * H, Ur, hB, q2, E, 1);

    // iteration 3: final h (no q needed)
    fused_gru_kernel<<<gE32, 256>>>(hB, q2, bg32, Pr, Pz, Ph,
                                    Wz + 384 * H, Wh + 384 * H, Ur, h_final, q1, E, 0);

    // output head: fused gather + dual-segment GEMM
    fused_node_kernel<<<gN64, 256>>>(fnode, Wo, h_final, ag32, bo, out_node, N);
}